// round 15
// baseline (speedup 1.0000x reference)
#include <cuda_runtime.h>
#include <cuda_bf16.h>
#include <cstdint>

#define HIDDEN   256
#define ATOM_DIM 133
#define BOND_DIM 14
#define MOL_DIM  200
#define N_ATOMS  120000
#define N_BONDS  240000
#define MAX_DEG  6
#define N_MOL    4096
#define OUT_COLS (HIDDEN + MOL_DIM)   // 456
#define EPS      1e-5f
#define NEG_SLOPE 0.01f
#define KC 32                          // K elements per smem chunk

// ---------------- device scratch (allocation-free) ---------------------------
__device__ float g_y0[(size_t)N_BONDS * HIDDEN];
__device__ float g_yhA[(size_t)N_BONDS * HIDDEN];
__device__ float g_yhB[(size_t)N_BONDS * HIDDEN];
__device__ float g_asum[(size_t)N_ATOMS * HIDDEN];
__device__ float g_yv[(size_t)N_ATOMS * HIDDEN];
__device__ __nv_bfloat16 g_WiH[256 * 160], g_WiL[256 * 160];   // K=147 -> 160
__device__ __nv_bfloat16 g_WmH[256 * 256], g_WmL[256 * 256];   // K=256
__device__ __nv_bfloat16 g_WaH[256 * 416], g_WaL[256 * 416];   // K=389 -> 416
__device__ float g_sum[HIDDEN];
__device__ float g_sumsq[HIDDEN];
__device__ float g_scale[5][HIDDEN];
__device__ float g_shift[5][HIDDEN];

// ---------------- PTX helpers ------------------------------------------------
__device__ __forceinline__ uint32_t smem_u32(const void* p) {
    uint32_t a;
    asm("{ .reg .u64 t; cvta.to.shared.u64 t, %1; cvt.u32.u64 %0, t; }" : "=r"(a) : "l"(p));
    return a;
}

#define LDSM_X4(r, addr) \
    asm volatile("ldmatrix.sync.aligned.m8n8.x4.shared.b16 {%0,%1,%2,%3}, [%4];" \
        : "=r"((r)[0]), "=r"((r)[1]), "=r"((r)[2]), "=r"((r)[3]) : "r"(addr))

#define MMA_BF16(d, a, b0, b1) \
    asm volatile("mma.sync.aligned.m16n8k16.row.col.f32.bf16.bf16.f32 " \
        "{%0,%1,%2,%3},{%4,%5,%6,%7},{%8,%9},{%0,%1,%2,%3};" \
        : "+f"((d)[0]), "+f"((d)[1]), "+f"((d)[2]), "+f"((d)[3]) \
        : "r"((a)[0]), "r"((a)[1]), "r"((a)[2]), "r"((a)[3]), "r"(b0), "r"(b1))

#define CP_ASYNC16(sa, gp) \
    asm volatile("cp.async.cg.shared.global [%0], [%1], 16;" :: "r"(sa), "l"(gp) : "memory")
#define CP_COMMIT() asm volatile("cp.async.commit_group;" ::: "memory")
#define CP_WAIT0()  asm volatile("cp.async.wait_group 0;" ::: "memory")

// ---------------- smem layout (bytes), DOUBLE buffered -----------------------
#define SA_BYTES 80
#define OFF_SRC  0
#define OFF_REV  256
#define OFF_CS   512
#define OFF_CSS  1536
#define OFF_A    2560
#define A_STAGE  10240                 // AH(5120) + AL(5120)
#define OFF_B    (OFF_A + 2 * A_STAGE) // 23040
#define B_STAGE  40960                 // BH(20480) + BL(20480)
#define SMEM_TOTAL (OFF_B + 2 * B_STAGE)   // 104960 (x2 CTAs = 209920 <= 228KB)

// ---------------- weight split-precision prep --------------------------------
__global__ void conv_w_kernel(const float* __restrict__ W,
                              __nv_bfloat16* __restrict__ BH,
                              __nv_bfloat16* __restrict__ BL, int K, int Kpad) {
    int idx = blockIdx.x * blockDim.x + threadIdx.x;
    if (idx >= 256 * Kpad) return;
    int n = idx / Kpad, k = idx % Kpad;
    float v = (k < K) ? __ldg(&W[n * K + k]) : 0.f;
    __nv_bfloat16 h = __float2bfloat16(v);
    BH[idx] = h;
    BL[idx] = __float2bfloat16(v - __bfloat162float(h));
}

// ---------------- HMMA fused GEMM, pipelined + gather-early ------------------
// Block: 64 rows x 256 cols. 8 warps, warp grid 2(m) x 4(n), warp tile m32 n64.
// MODE 0: h0     A[b,k] = k<14 ? bond_f : atom_f[src[b]]            K->160
// MODE 1: msg    A[b,k] = asum[src[b],k] - (yprev[rev[b],k]*sc+sh)  K=256, +h0 res
// MODE 2: final  A[v,k] = k<133 ? atom_f[v] : m_v[v,k-133]          K->416
template <int MODE>
__global__ __launch_bounds__(256, 2)
void gemm_mma(int nChunks,
              const float* __restrict__ bondf, const float* __restrict__ atomf,
              const int* __restrict__ src, const int* __restrict__ rev,
              const float* __restrict__ gmat, const float* __restrict__ yprev,
              const float* __restrict__ scp, const float* __restrict__ shp,
              const float* __restrict__ y0,
              const float* __restrict__ sc0, const float* __restrict__ sh0,
              const __nv_bfloat16* __restrict__ BH, const __nv_bfloat16* __restrict__ BL,
              int Kpad,
              const float* __restrict__ bias,
              float* __restrict__ yout) {
    extern __shared__ __align__(128) char smem[];
    const uint32_t sb = smem_u32(smem);
    const int tid = threadIdx.x;
    const int wid = tid >> 5;
    const int lane = tid & 31;
    const int wr = wid & 1;          // warp row (2 x 32 rows)
    const int wc = wid >> 1;         // warp col (4 x 64 cols)
    const int row0 = blockIdx.x * 64;

    int* s_src = (int*)(smem + OFF_SRC);
    int* s_rev = (int*)(smem + OFF_REV);
    float* s_cs = (float*)(smem + OFF_CS);
    float* s_css = (float*)(smem + OFF_CSS);

    if (MODE != 2) { if (tid < 64) s_src[tid] = __ldg(&src[row0 + tid]); }
    if (MODE == 1) { if (tid >= 64 && tid < 128) s_rev[tid - 64] = __ldg(&rev[row0 + tid - 64]); }
    s_cs[tid] = 0.f;
    s_css[tid] = 0.f;
    __syncthreads();   // s_src visible before any gather

    float acc[2][8][4];
#pragma unroll
    for (int t = 0; t < 2; t++)
#pragma unroll
        for (int j = 0; j < 8; j++)
#pragma unroll
            for (int e = 0; e < 4; e++) acc[t][j][e] = 0.f;

    // gather indices for A-tile loads: thread -> (row, 8-k segment)
    const int grow = tid >> 2;
    const int gks  = (tid & 3) * 8;

    // ldmatrix lane addressing (constant across chunks)
    const uint32_t a_row = (uint32_t)(wr * 32 + (lane & 15));
    const uint32_t a_kc8 = (uint32_t)((lane >> 4) * 8);
    const uint32_t b_nrow = (uint32_t)(wc * 64 + ((lane >> 4) & 1) * 8 + (lane & 7));
    const uint32_t b_kc8 = (uint32_t)(((lane >> 3) & 1) * 8);

    // ---- stage helpers ----
    auto loadB = [&](int c, int st) {   // cp.async weights -> buf[st], commit
        const size_t gbase = (size_t)tid * Kpad + c * KC;
        const uint32_t sbase = sb + OFF_B + (uint32_t)st * B_STAGE + (uint32_t)tid * SA_BYTES;
#pragma unroll
        for (int j = 0; j < 4; j++) {
            CP_ASYNC16(sbase + j * 16,         BH + gbase + j * 8);
            CP_ASYNC16(sbase + 20480 + j * 16, BL + gbase + j * 8);
        }
        CP_COMMIT();
    };

    // issue phase: start the gather LDGs; results consumed after the MMA phase
    float4 ra0, ra1, ry0, ry1;    // MODE 1 raw loads
    float  v[8];                  // MODE 0/2 values (predicated loads)
    auto gatherIssue = [&](int c) {
        const int k0 = c * KC;
        if (MODE == 1) {
            const float* ga = gmat  + (size_t)s_src[grow] * HIDDEN + k0 + gks;
            const float* yy = yprev + (size_t)s_rev[grow] * HIDDEN + k0 + gks;
            ra0 = __ldg((const float4*)ga);
            ra1 = __ldg((const float4*)(ga + 4));
            ry0 = __ldg((const float4*)yy);
            ry1 = __ldg((const float4*)(yy + 4));
        } else {
#pragma unroll
            for (int e = 0; e < 8; e++) {
                const int kk = k0 + gks + e;
                float x = 0.f;
                if (MODE == 0) {
                    if (kk < BOND_DIM)
                        x = __ldg(&bondf[(size_t)(row0 + grow) * BOND_DIM + kk]);
                    else if (kk < BOND_DIM + ATOM_DIM)
                        x = __ldg(&atomf[(size_t)s_src[grow] * ATOM_DIM + kk - BOND_DIM]);
                } else {
                    if (kk < ATOM_DIM)
                        x = __ldg(&atomf[(size_t)(row0 + grow) * ATOM_DIM + kk]);
                    else if (kk < ATOM_DIM + HIDDEN)
                        x = __ldg(&gmat[(size_t)(row0 + grow) * HIDDEN + kk - ATOM_DIM]);
                }
                v[e] = x;
            }
        }
    };

    // finish phase: fold (MODE1), split hi/lo, store to A buf[st]
    auto gatherFinish = [&](int c, int st) {
        const int k0 = c * KC;
        if (MODE == 1) {
            const float4 sc4 = __ldg((const float4*)(scp + k0 + gks));
            const float4 sc5 = __ldg((const float4*)(scp + k0 + gks + 4));
            const float4 sh4 = __ldg((const float4*)(shp + k0 + gks));
            const float4 sh5 = __ldg((const float4*)(shp + k0 + gks + 4));
            v[0] = ra0.x - fmaf(ry0.x, sc4.x, sh4.x);
            v[1] = ra0.y - fmaf(ry0.y, sc4.y, sh4.y);
            v[2] = ra0.z - fmaf(ry0.z, sc4.z, sh4.z);
            v[3] = ra0.w - fmaf(ry0.w, sc4.w, sh4.w);
            v[4] = ra1.x - fmaf(ry1.x, sc5.x, sh5.x);
            v[5] = ra1.y - fmaf(ry1.y, sc5.y, sh5.y);
            v[6] = ra1.z - fmaf(ry1.z, sc5.z, sh5.z);
            v[7] = ra1.w - fmaf(ry1.w, sc5.w, sh5.w);
        }
        __nv_bfloat16 hh[8], ll[8];
#pragma unroll
        for (int e = 0; e < 8; e++) {
            hh[e] = __float2bfloat16(v[e]);
            ll[e] = __float2bfloat16(v[e] - __bfloat162float(hh[e]));
        }
        const uint32_t off = OFF_A + (uint32_t)st * A_STAGE + (uint32_t)grow * SA_BYTES + (uint32_t)gks * 2;
        *(uint4*)(smem + off)        = *(const uint4*)hh;
        *(uint4*)(smem + off + 5120) = *(const uint4*)ll;
    };

    // ---- prologue: fill stage 0 ----
    gatherIssue(0);
    gatherFinish(0, 0);
    loadB(0, 0);

    // ---- pipelined mainloop: ONE sync per chunk; gather LDGs overlap MMAs ----
    for (int c = 0; c < nChunks; ++c) {
        const int st = c & 1, nx = st ^ 1;
        CP_WAIT0();          // B(c) landed
        __syncthreads();     // A(c)/B(c) visible; MMA(c-1) reads of buf[nx] done
        const bool more = (c + 1 < nChunks);
        if (more) {
            loadB(c + 1, nx);
            gatherIssue(c + 1);   // LDGs in flight across the MMA phase below
        }

        const uint32_t abase = sb + OFF_A + (uint32_t)st * A_STAGE;
        const uint32_t bbase = sb + OFF_B + (uint32_t)st * B_STAGE;
#pragma unroll
        for (int s = 0; s < 2; ++s) {
            uint32_t aH[2][4], aL[2][4];
            const uint32_t aoff = a_row * SA_BYTES + (s * 16 + a_kc8) * 2;
            LDSM_X4(aH[0], abase + aoff);
            LDSM_X4(aH[1], abase + aoff + 16 * SA_BYTES);
            LDSM_X4(aL[0], abase + 5120 + aoff);
            LDSM_X4(aL[1], abase + 5120 + aoff + 16 * SA_BYTES);

#pragma unroll
            for (int p = 0; p < 4; p++) {
                uint32_t bh[4], bl[4];
                const uint32_t boff = (b_nrow + p * 16) * SA_BYTES + (s * 16 + b_kc8) * 2;
                LDSM_X4(bh, bbase + boff);
                LDSM_X4(bl, bbase + 20480 + boff);
                // hi*hi
                MMA_BF16(acc[0][2 * p],     aH[0], bh[0], bh[1]);
                MMA_BF16(acc[0][2 * p + 1], aH[0], bh[2], bh[3]);
                MMA_BF16(acc[1][2 * p],     aH[1], bh[0], bh[1]);
                MMA_BF16(acc[1][2 * p + 1], aH[1], bh[2], bh[3]);
                // hi*lo
                MMA_BF16(acc[0][2 * p],     aH[0], bl[0], bl[1]);
                MMA_BF16(acc[0][2 * p + 1], aH[0], bl[2], bl[3]);
                MMA_BF16(acc[1][2 * p],     aH[1], bl[0], bl[1]);
                MMA_BF16(acc[1][2 * p + 1], aH[1], bl[2], bl[3]);
                // lo*hi
                MMA_BF16(acc[0][2 * p],     aL[0], bh[0], bh[1]);
                MMA_BF16(acc[0][2 * p + 1], aL[0], bh[2], bh[3]);
                MMA_BF16(acc[1][2 * p],     aL[1], bh[0], bh[1]);
                MMA_BF16(acc[1][2 * p + 1], aL[1], bh[2], bh[3]);
            }
        }

        if (more) gatherFinish(c + 1, nx);   // loads have had the MMA phase to land
    }

    // ---- epilogue: bias (+residual), leaky, store, batch stats ----
#pragma unroll
    for (int j = 0; j < 8; ++j) {
        const int cc = wc * 64 + j * 8 + (lane & 3) * 2;
        const float2 b2 = __ldg((const float2*)(bias + cc));
        float sc0c = 0.f, sc0c1 = 0.f, sh0c = 0.f, sh0c1 = 0.f;
        if (MODE == 1) {
            const float2 s2 = __ldg((const float2*)(sc0 + cc));
            const float2 h2 = __ldg((const float2*)(sh0 + cc));
            sc0c = s2.x; sc0c1 = s2.y; sh0c = h2.x; sh0c1 = h2.y;
        }
        float s0 = 0.f, s1 = 0.f, q0 = 0.f, q1 = 0.f;
#pragma unroll
        for (int t = 0; t < 2; ++t) {
            const size_t r0 = (size_t)row0 + wr * 32 + t * 16 + (lane >> 2);
            const size_t r1 = r0 + 8;
            float v00 = acc[t][j][0] + b2.x;
            float v01 = acc[t][j][1] + b2.y;
            float v10 = acc[t][j][2] + b2.x;
            float v11 = acc[t][j][3] + b2.y;
            if (MODE == 1) {
                const float2 ya = __ldg((const float2*)(y0 + r0 * HIDDEN + cc));
                const float2 yb = __ldg((const float2*)(y0 + r1 * HIDDEN + cc));
                v00 += fmaf(ya.x, sc0c, sh0c);
                v01 += fmaf(ya.y, sc0c1, sh0c1);
                v10 += fmaf(yb.x, sc0c, sh0c);
                v11 += fmaf(yb.y, sc0c1, sh0c1);
            }
            v00 = v00 >= 0.f ? v00 : NEG_SLOPE * v00;
            v01 = v01 >= 0.f ? v01 : NEG_SLOPE * v01;
            v10 = v10 >= 0.f ? v10 : NEG_SLOPE * v10;
            v11 = v11 >= 0.f ? v11 : NEG_SLOPE * v11;
            *(float2*)(yout + r0 * HIDDEN + cc) = make_float2(v00, v01);
            *(float2*)(yout + r1 * HIDDEN + cc) = make_float2(v10, v11);
            s0 += v00 + v10;
            s1 += v01 + v11;
            q0 += v00 * v00 + v10 * v10;
            q1 += v01 * v01 + v11 * v11;
        }
#pragma unroll
        for (int d = 4; d <= 16; d <<= 1) {
            s0 += __shfl_xor_sync(0xffffffffu, s0, d);
            s1 += __shfl_xor_sync(0xffffffffu, s1, d);
            q0 += __shfl_xor_sync(0xffffffffu, q0, d);
            q1 += __shfl_xor_sync(0xffffffffu, q1, d);
        }
        if ((lane >> 2) == 0) {
            atomicAdd(&s_cs[cc], s0);
            atomicAdd(&s_cs[cc + 1], s1);
            atomicAdd(&s_css[cc], q0);
            atomicAdd(&s_css[cc + 1], q1);
        }
    }
    __syncthreads();
    atomicAdd(&g_sum[tid], s_cs[tid]);
    atomicAdd(&g_sumsq[tid], s_css[tid]);
}

// ---------------- BN finalize ------------------------------------------------
__global__ void finalize_kernel(const float* __restrict__ bnw,
                                const float* __restrict__ bnb,
                                float inv_n,
                                float* __restrict__ sc_out,
                                float* __restrict__ sh_out) {
    int o = threadIdx.x;
    float s = g_sum[o], ss = g_sumsq[o];
    float mu = s * inv_n;
    float var = fmaxf(ss * inv_n - mu * mu, 0.f);
    float sc = __ldg(&bnw[o]) * rsqrtf(var + EPS);
    sc_out[o] = sc;
    sh_out[o] = __ldg(&bnb[o]) - mu * sc;
    g_sum[o] = 0.f;
    g_sumsq[o] = 0.f;
}

// ---------------- atom incoming sums (normalized) ----------------------------
__global__ void atom_sum_kernel(const float* __restrict__ y,
                                const int* __restrict__ aibm,
                                const float* __restrict__ sc,
                                const float* __restrict__ sh,
                                float* __restrict__ outp) {
    int gw = (blockIdx.x * blockDim.x + threadIdx.x) >> 5;
    int lane = threadIdx.x & 31;
    if (gw >= N_ATOMS) return;
    float a0 = 0, a1 = 0, a2 = 0, a3 = 0;
    float b0 = 0, b1 = 0, b2 = 0, b3 = 0;
    float cnt = 0.f;
#pragma unroll
    for (int j = 0; j < MAX_DEG; j++) {
        int id = __ldg(&aibm[gw * MAX_DEG + j]);
        if (id > 0) {
            const float4* r = (const float4*)(y + (size_t)(id - 1) * HIDDEN);
            float4 v = __ldg(&r[lane]);
            a0 += v.x; a1 += v.y; a2 += v.z; a3 += v.w;
            float4 w = __ldg(&r[lane + 32]);
            b0 += w.x; b1 += w.y; b2 += w.z; b3 += w.w;
            cnt += 1.f;
        }
    }
    float4 s0 = __ldg((const float4*)sc + lane);
    float4 h0 = __ldg((const float4*)sh + lane);
    float4 s1 = __ldg((const float4*)sc + lane + 32);
    float4 h1 = __ldg((const float4*)sh + lane + 32);
    float4* o = (float4*)(outp + (size_t)gw * HIDDEN);
    o[lane]      = make_float4(fmaf(a0, s0.x, cnt * h0.x), fmaf(a1, s0.y, cnt * h0.y),
                               fmaf(a2, s0.z, cnt * h0.z), fmaf(a3, s0.w, cnt * h0.w));
    o[lane + 32] = make_float4(fmaf(b0, s1.x, cnt * h1.x), fmaf(b1, s1.y, cnt * h1.y),
                               fmaf(b2, s1.z, cnt * h1.z), fmaf(b3, s1.w, cnt * h1.w));
}

// ---------------- output init + pooling --------------------------------------
__global__ void out_init_kernel(const float* __restrict__ molf,
                                float* __restrict__ out) {
    int idx = blockIdx.x * blockDim.x + threadIdx.x;
    if (idx >= N_MOL * OUT_COLS) return;
    int m = idx / OUT_COLS, c = idx % OUT_COLS;
    out[idx] = (c < HIDDEN) ? 0.f : __ldg(&molf[m * MOL_DIM + (c - HIDDEN)]);
}

__global__ void pool_kernel(const float* __restrict__ yv,
                            const int* __restrict__ a2m,
                            const float* __restrict__ sc,
                            const float* __restrict__ sh,
                            float* __restrict__ out) {
    __shared__ int s_mol[32];
    const int c = threadIdx.x;
    const int a0 = blockIdx.x * 32;
    if (c < 32) s_mol[c] = __ldg(&a2m[a0 + c]);
    __syncthreads();
    const float scc = __ldg(&sc[c]);
    const float shc = __ldg(&sh[c]);
    int run = s_mol[0];
    float acc = 0.f;
#pragma unroll 4
    for (int a = 0; a < 32; a++) {
        int m = s_mol[a];
        if (m != run) {
            atomicAdd(&out[(size_t)run * OUT_COLS + c], acc);
            acc = 0.f;
            run = m;
        }
        acc = fmaf(__ldg(&yv[(size_t)(a0 + a) * HIDDEN + c]), scc, acc + shc);
    }
    atomicAdd(&out[(size_t)run * OUT_COLS + c], acc);
}

// ---------------- host launcher ----------------------------------------------
extern "C" void kernel_launch(void* const* d_in, const int* in_sizes, int n_in,
                              void* d_out, int out_size) {
    const float* atomf = (const float*)d_in[0];
    const float* bondf = (const float*)d_in[1];
    const int*   bidx  = (const int*)d_in[2];
    const float* molf  = (const float*)d_in[3];
    const int*   aibm  = (const int*)d_in[4];
    const int*   rev   = (const int*)d_in[5];
    const int*   a2m   = (const int*)d_in[6];
    const float* Wi    = (const float*)d_in[7];
    const float* bi    = (const float*)d_in[8];
    const float* Wm    = (const float*)d_in[9];
    const float* bm    = (const float*)d_in[10];
    const float* Wa    = (const float*)d_in[11];
    const float* ba    = (const float*)d_in[12];
    const float* bnw   = (const float*)d_in[13];
    const float* bnb   = (const float*)d_in[14];
    const int* src = bidx;
    float* out = (float*)d_out;

    float *p_y0, *p_yhA, *p_yhB, *p_asum, *p_yv, *p_sc, *p_sh;
    __nv_bfloat16 *p_WiH, *p_WiL, *p_WmH, *p_WmL, *p_WaH, *p_WaL;
    cudaGetSymbolAddress((void**)&p_y0, g_y0);
    cudaGetSymbolAddress((void**)&p_yhA, g_yhA);
    cudaGetSymbolAddress((void**)&p_yhB, g_yhB);
    cudaGetSymbolAddress((void**)&p_asum, g_asum);
    cudaGetSymbolAddress((void**)&p_yv, g_yv);
    cudaGetSymbolAddress((void**)&p_WiH, g_WiH);
    cudaGetSymbolAddress((void**)&p_WiL, g_WiL);
    cudaGetSymbolAddress((void**)&p_WmH, g_WmH);
    cudaGetSymbolAddress((void**)&p_WmL, g_WmL);
    cudaGetSymbolAddress((void**)&p_WaH, g_WaH);
    cudaGetSymbolAddress((void**)&p_WaL, g_WaL);
    cudaGetSymbolAddress((void**)&p_sc, g_scale);
    cudaGetSymbolAddress((void**)&p_sh, g_shift);
    auto SC = [&](int s) { return p_sc + s * HIDDEN; };
    auto SH = [&](int s) { return p_sh + s * HIDDEN; };

    cudaFuncSetAttribute(gemm_mma<0>, cudaFuncAttributeMaxDynamicSharedMemorySize, SMEM_TOTAL);
    cudaFuncSetAttribute(gemm_mma<1>, cudaFuncAttributeMaxDynamicSharedMemorySize, SMEM_TOTAL);
    cudaFuncSetAttribute(gemm_mma<2>, cudaFuncAttributeMaxDynamicSharedMemorySize, SMEM_TOTAL);

    // split-precision weight prep
    conv_w_kernel<<<(256 * 160 + 255) / 256, 256>>>(Wi, p_WiH, p_WiL, 147, 160);
    conv_w_kernel<<<(256 * 256 + 255) / 256, 256>>>(Wm, p_WmH, p_WmL, 256, 256);
    conv_w_kernel<<<(256 * 416 + 255) / 256, 256>>>(Wa, p_WaH, p_WaL, 389, 416);

    const int GB = N_BONDS / 64;   // 3750
    const int GA = N_ATOMS / 64;   // 1875

    // stage 0: h0
    gemm_mma<0><<<GB, 256, SMEM_TOTAL>>>(5, bondf, atomf, src, nullptr,
                                         nullptr, nullptr, nullptr, nullptr,
                                         nullptr, nullptr, nullptr,
                                         p_WiH, p_WiL, 160, bi, p_y0);
    finalize_kernel<<<1, 256>>>(bnw, bnb, 1.f / N_BONDS, SC(0), SH(0));

    // depth iterations
    float* ybuf[4] = {p_y0, p_yhA, p_yhB, p_yhA};
    for (int d = 0; d < 3; d++) {
        float* yin = ybuf[d];
        float* yot = ybuf[d + 1];
        atom_sum_kernel<<<N_ATOMS / 8, 256>>>(yin, aibm, SC(d), SH(d), p_asum);
        gemm_mma<1><<<GB, 256, SMEM_TOTAL>>>(8, nullptr, nullptr, src, rev,
                                             p_asum, yin, SC(d), SH(d),
                                             p_y0, SC(0), SH(0),
                                             p_WmH, p_WmL, 256, bm, yot);
        finalize_kernel<<<1, 256>>>(bnw, bnb, 1.f / N_BONDS, SC(d + 1), SH(d + 1));
    }

    // final atom readout
    atom_sum_kernel<<<N_ATOMS / 8, 256>>>(ybuf[3], aibm, SC(3), SH(3), p_asum);
    gemm_mma<2><<<GA, 256, SMEM_TOTAL>>>(13, nullptr, atomf, nullptr, nullptr,
                                         p_asum, nullptr, nullptr, nullptr,
                                         nullptr, nullptr, nullptr,
                                         p_WaH, p_WaL, 416, ba, p_yv);
    finalize_kernel<<<1, 256>>>(bnw, bnb, 1.f / N_ATOMS, SC(4), SH(4));

    // molecule pooling + feature concat
    out_init_kernel<<<(N_MOL * OUT_COLS + 255) / 256, 256>>>(molf, out);
    pool_kernel<<<N_ATOMS / 32, 256>>>(p_yv, a2m, SC(4), SH(4), out);
}

// round 16
// speedup vs baseline: 1.0926x; 1.0926x over previous
#include <cuda_runtime.h>
#include <cuda_bf16.h>
#include <cstdint>

#define HIDDEN   256
#define ATOM_DIM 133
#define BOND_DIM 14
#define MOL_DIM  200
#define N_ATOMS  120000
#define N_BONDS  240000
#define MAX_DEG  6
#define N_MOL    4096
#define OUT_COLS (HIDDEN + MOL_DIM)   // 456
#define EPS      1e-5f
#define NEG_SLOPE 0.01f
#define KC 32                          // K elements per smem chunk
#define THREADS 512
#define BM 128

// ---------------- device scratch (allocation-free) ---------------------------
__device__ float g_y0[(size_t)N_BONDS * HIDDEN];
__device__ float g_yhA[(size_t)N_BONDS * HIDDEN];
__device__ float g_yhB[(size_t)N_BONDS * HIDDEN];
__device__ float g_asum[(size_t)N_ATOMS * HIDDEN];
__device__ float g_yv[(size_t)N_ATOMS * HIDDEN];
__device__ __nv_bfloat16 g_WiH[256 * 160], g_WiL[256 * 160];   // K=147 -> 160
__device__ __nv_bfloat16 g_WmH[256 * 256], g_WmL[256 * 256];   // K=256
__device__ __nv_bfloat16 g_WaH[256 * 416], g_WaL[256 * 416];   // K=389 -> 416
__device__ float g_sum[HIDDEN];
__device__ float g_sumsq[HIDDEN];
__device__ float g_scale[5][HIDDEN];
__device__ float g_shift[5][HIDDEN];

// ---------------- PTX helpers ------------------------------------------------
__device__ __forceinline__ uint32_t smem_u32(const void* p) {
    uint32_t a;
    asm("{ .reg .u64 t; cvta.to.shared.u64 t, %1; cvt.u32.u64 %0, t; }" : "=r"(a) : "l"(p));
    return a;
}

#define LDSM_X4(r, addr) \
    asm volatile("ldmatrix.sync.aligned.m8n8.x4.shared.b16 {%0,%1,%2,%3}, [%4];" \
        : "=r"((r)[0]), "=r"((r)[1]), "=r"((r)[2]), "=r"((r)[3]) : "r"(addr))

#define MMA_BF16(d, a, b0, b1) \
    asm volatile("mma.sync.aligned.m16n8k16.row.col.f32.bf16.bf16.f32 " \
        "{%0,%1,%2,%3},{%4,%5,%6,%7},{%8,%9},{%0,%1,%2,%3};" \
        : "+f"((d)[0]), "+f"((d)[1]), "+f"((d)[2]), "+f"((d)[3]) \
        : "r"((a)[0]), "r"((a)[1]), "r"((a)[2]), "r"((a)[3]), "r"(b0), "r"(b1))

#define CP_ASYNC16(sa, gp) \
    asm volatile("cp.async.cg.shared.global [%0], [%1], 16;" :: "r"(sa), "l"(gp) : "memory")
#define CP_COMMIT() asm volatile("cp.async.commit_group;" ::: "memory")
#define CP_WAIT0()  asm volatile("cp.async.wait_group 0;" ::: "memory")

// ---------------- smem layout (bytes) ----------------------------------------
// A tile: 128 rows x 32k bf16, stride 80B; hi + lo halves; double buffered
// B tile: 256 rows x 32k bf16, stride 80B; hi + lo halves; double buffered
// RAW (MODE1): 128 rows x (128B asum + 128B yprev + 16B pad) = 272B; double
#define SA_BYTES 80
#define OFF_SRC   0
#define OFF_REV   512
#define OFF_SC    1024
#define OFF_SH    2048
#define OFF_CS    3072
#define OFF_CSS   4096
#define OFF_A     5120
#define A_HALF    10240                 // 128*80
#define A_STAGE   20480                 // hi + lo
#define OFF_B     (OFF_A + 2 * A_STAGE)     // 46080
#define B_HALF    20480                 // 256*80
#define B_STAGE   40960
#define OFF_RAW   (OFF_B + 2 * B_STAGE)     // 128000
#define RAW_STRIDE 272
#define RAW_STAGE (BM * RAW_STRIDE)     // 34816
#define SMEM_TOTAL (OFF_RAW + 2 * RAW_STAGE)   // 197632

// ---------------- weight split-precision prep --------------------------------
__global__ void conv_w_kernel(const float* __restrict__ W,
                              __nv_bfloat16* __restrict__ BH,
                              __nv_bfloat16* __restrict__ BL, int K, int Kpad) {
    int idx = blockIdx.x * blockDim.x + threadIdx.x;
    if (idx >= 256 * Kpad) return;
    int n = idx / Kpad, k = idx % Kpad;
    float v = (k < K) ? __ldg(&W[n * K + k]) : 0.f;
    __nv_bfloat16 h = __float2bfloat16(v);
    BH[idx] = h;
    BL[idx] = __float2bfloat16(v - __bfloat162float(h));
}

// ---------------- HMMA fused GEMM: cp.async-staged gather --------------------
// Block: 128 rows x 256 cols. 16 warps, warp grid 4(m) x 4(n), tile m32 n64.
// MODE 0: h0     A[b,k] = k<14 ? bond_f : atom_f[src[b]]            K->160
// MODE 1: msg    A[b,k] = asum[src[b],k] - (yprev[rev[b],k]*sc+sh)  K=256, +h0 res
// MODE 2: final  A[v,k] = k<133 ? atom_f[v] : m_v[v,k-133]          K->416
template <int MODE>
__global__ __launch_bounds__(THREADS, 1)
void gemm_mma(int nChunks,
              const float* __restrict__ bondf, const float* __restrict__ atomf,
              const int* __restrict__ src, const int* __restrict__ rev,
              const float* __restrict__ gmat, const float* __restrict__ yprev,
              const float* __restrict__ scp, const float* __restrict__ shp,
              const float* __restrict__ y0,
              const float* __restrict__ sc0, const float* __restrict__ sh0,
              const __nv_bfloat16* __restrict__ BH, const __nv_bfloat16* __restrict__ BL,
              int Kpad,
              const float* __restrict__ bias,
              float* __restrict__ yout) {
    extern __shared__ __align__(128) char smem[];
    const uint32_t sb = smem_u32(smem);
    const int tid = threadIdx.x;
    const int wid = tid >> 5;
    const int lane = tid & 31;
    const int wr = wid & 3;          // warp row (4 x 32 rows)
    const int wc = wid >> 2;         // warp col (4 x 64 cols)
    const int row0 = blockIdx.x * BM;

    int* s_src = (int*)(smem + OFF_SRC);
    int* s_rev = (int*)(smem + OFF_REV);
    float* s_sc = (float*)(smem + OFF_SC);
    float* s_sh = (float*)(smem + OFF_SH);
    float* s_cs = (float*)(smem + OFF_CS);
    float* s_css = (float*)(smem + OFF_CSS);

    if (MODE != 2) {
        if (tid < BM) s_src[tid] = __ldg(&src[row0 + tid]);
    }
    if (MODE == 1) {
        if (tid >= BM && tid < 2 * BM) s_rev[tid - BM] = __ldg(&rev[row0 + tid - BM]);
        if (tid >= 256) { s_sc[tid - 256] = __ldg(&scp[tid - 256]); }
    }
    if (tid < 256) {
        s_cs[tid] = 0.f;
        s_css[tid] = 0.f;
        if (MODE == 1) s_sh[tid] = __ldg(&shp[tid]);
    }
    __syncthreads();

    float acc[2][8][4];
#pragma unroll
    for (int t = 0; t < 2; t++)
#pragma unroll
        for (int j = 0; j < 8; j++)
#pragma unroll
            for (int e = 0; e < 4; e++) acc[t][j][e] = 0.f;

    // gather thread mapping: row + 8-elem k segment
    const int grow = tid >> 2;            // 0..127
    const int gks  = (tid & 3) * 8;       // 0,8,16,24

    // ldmatrix lane addressing
    const uint32_t a_row = (uint32_t)(wr * 32 + (lane & 15));
    const uint32_t a_kc8 = (uint32_t)((lane >> 4) * 8);
    const uint32_t b_nrow = (uint32_t)(wc * 64 + ((lane >> 4) & 1) * 8 + (lane & 7));
    const uint32_t b_kc8 = (uint32_t)(((lane >> 3) & 1) * 8);

    // ---- issue raw-gather (MODE1) + B weights for chunk c into stage st ----
    auto issueG = [&](int c, int st) {
        const int kn = c * KC;
        if (MODE == 1) {
            const float* pa = gmat  + (size_t)s_src[grow] * HIDDEN + kn + gks;
            const float* py = yprev + (size_t)s_rev[grow] * HIDDEN + kn + gks;
            const uint32_t rdst = sb + OFF_RAW + (uint32_t)st * RAW_STAGE
                                + (uint32_t)grow * RAW_STRIDE + (uint32_t)(tid & 3) * 32;
            CP_ASYNC16(rdst,       pa);
            CP_ASYNC16(rdst + 16,  pa + 4);
            CP_ASYNC16(rdst + 128, py);
            CP_ASYNC16(rdst + 144, py + 4);
        }
        {
            const int brow = tid >> 1;
            const int bo = (tid & 1) * 16;
            const size_t gb = (size_t)brow * Kpad + kn + bo;
            const uint32_t bdst = sb + OFF_B + (uint32_t)st * B_STAGE
                                + (uint32_t)brow * SA_BYTES + (uint32_t)bo * 2;
            CP_ASYNC16(bdst,               BH + gb);
            CP_ASYNC16(bdst + 16,          BH + gb + 8);
            CP_ASYNC16(bdst + B_HALF,      BL + gb);
            CP_ASYNC16(bdst + B_HALF + 16, BL + gb + 8);
        }
        CP_COMMIT();
    };

    // ---- convert: raw/global -> split bf16 -> A tile (stage st) ----
    auto convert = [&](int c, int st) {
        const int k0 = c * KC;
        float v[8];
        if (MODE == 1) {
            const char* rb = smem + OFF_RAW + (size_t)st * RAW_STAGE
                           + (size_t)grow * RAW_STRIDE + (size_t)(tid & 3) * 32;
            const float4 a4 = *(const float4*)(rb);
            const float4 a5 = *(const float4*)(rb + 16);
            const float4 y4 = *(const float4*)(rb + 128);
            const float4 y5 = *(const float4*)(rb + 144);
            const float4 sc4 = *(const float4*)(s_sc + k0 + gks);
            const float4 sc5 = *(const float4*)(s_sc + k0 + gks + 4);
            const float4 sh4 = *(const float4*)(s_sh + k0 + gks);
            const float4 sh5 = *(const float4*)(s_sh + k0 + gks + 4);
            v[0] = a4.x - fmaf(y4.x, sc4.x, sh4.x);
            v[1] = a4.y - fmaf(y4.y, sc4.y, sh4.y);
            v[2] = a4.z - fmaf(y4.z, sc4.z, sh4.z);
            v[3] = a4.w - fmaf(y4.w, sc4.w, sh4.w);
            v[4] = a5.x - fmaf(y5.x, sc5.x, sh5.x);
            v[5] = a5.y - fmaf(y5.y, sc5.y, sh5.y);
            v[6] = a5.z - fmaf(y5.z, sc5.z, sh5.z);
            v[7] = a5.w - fmaf(y5.w, sc5.w, sh5.w);
        } else {
#pragma unroll
            for (int e = 0; e < 8; e++) {
                const int kk = k0 + gks + e;
                float x = 0.f;
                if (MODE == 0) {
                    if (kk < BOND_DIM)
                        x = __ldg(&bondf[(size_t)(row0 + grow) * BOND_DIM + kk]);
                    else if (kk < BOND_DIM + ATOM_DIM)
                        x = __ldg(&atomf[(size_t)s_src[grow] * ATOM_DIM + kk - BOND_DIM]);
                } else {
                    if (row0 + grow < N_ATOMS) {
                        if (kk < ATOM_DIM)
                            x = __ldg(&atomf[(size_t)(row0 + grow) * ATOM_DIM + kk]);
                        else if (kk < ATOM_DIM + HIDDEN)
                            x = __ldg(&gmat[(size_t)(row0 + grow) * HIDDEN + kk - ATOM_DIM]);
                    }
                }
                v[e] = x;
            }
        }
        __nv_bfloat16 hh[8], ll[8];
#pragma unroll
        for (int e = 0; e < 8; e++) {
            hh[e] = __float2bfloat16(v[e]);
            ll[e] = __float2bfloat16(v[e] - __bfloat162float(hh[e]));
        }
        char* ab = smem + OFF_A + (size_t)st * A_STAGE
                 + (size_t)grow * SA_BYTES + (size_t)gks * 2;
        *(uint4*)(ab)          = *(const uint4*)hh;
        *(uint4*)(ab + A_HALF) = *(const uint4*)ll;
    };

    // ---- prologue ----
    issueG(0, 0);

    // ---- mainloop ----
    for (int c = 0; c < nChunks; ++c) {
        const int st = c & 1, nx = st ^ 1;
        CP_WAIT0();          // raw(c)/B(c) landed
        __syncthreads();     // all warps past MMA(c-1); cp.async data visible
        convert(c, st);
        if (c + 1 < nChunks) issueG(c + 1, nx);   // runs behind the MMA phase
        __syncthreads();     // A(c) visible

        const uint32_t abase = sb + OFF_A + (uint32_t)st * A_STAGE;
        const uint32_t bbase = sb + OFF_B + (uint32_t)st * B_STAGE;
#pragma unroll
        for (int s = 0; s < 2; ++s) {
            uint32_t aH[2][4], aL[2][4];
            const uint32_t aoff = a_row * SA_BYTES + (s * 16 + a_kc8) * 2;
            LDSM_X4(aH[0], abase + aoff);
            LDSM_X4(aH[1], abase + aoff + 16 * SA_BYTES);
            LDSM_X4(aL[0], abase + A_HALF + aoff);
            LDSM_X4(aL[1], abase + A_HALF + aoff + 16 * SA_BYTES);

#pragma unroll
            for (int p = 0; p < 4; p++) {
                uint32_t bh[4], bl[4];
                const uint32_t boff = (b_nrow + p * 16) * SA_BYTES + (s * 16 + b_kc8) * 2;
                LDSM_X4(bh, bbase + boff);
                LDSM_X4(bl, bbase + B_HALF + boff);
                // hi*hi
                MMA_BF16(acc[0][2 * p],     aH[0], bh[0], bh[1]);
                MMA_BF16(acc[0][2 * p + 1], aH[0], bh[2], bh[3]);
                MMA_BF16(acc[1][2 * p],     aH[1], bh[0], bh[1]);
                MMA_BF16(acc[1][2 * p + 1], aH[1], bh[2], bh[3]);
                // hi*lo
                MMA_BF16(acc[0][2 * p],     aH[0], bl[0], bl[1]);
                MMA_BF16(acc[0][2 * p + 1], aH[0], bl[2], bl[3]);
                MMA_BF16(acc[1][2 * p],     aH[1], bl[0], bl[1]);
                MMA_BF16(acc[1][2 * p + 1], aH[1], bl[2], bl[3]);
                // lo*hi
                MMA_BF16(acc[0][2 * p],     aL[0], bh[0], bh[1]);
                MMA_BF16(acc[0][2 * p + 1], aL[0], bh[2], bh[3]);
                MMA_BF16(acc[1][2 * p],     aL[1], bh[0], bh[1]);
                MMA_BF16(acc[1][2 * p + 1], aL[1], bh[2], bh[3]);
            }
        }
    }

    // ---- epilogue: bias (+residual), leaky, store, batch stats ----
#pragma unroll
    for (int j = 0; j < 8; ++j) {
        const int cc = wc * 64 + j * 8 + (lane & 3) * 2;
        const float2 b2 = __ldg((const float2*)(bias + cc));
        float sc0c = 0.f, sc0c1 = 0.f, sh0c = 0.f, sh0c1 = 0.f;
        if (MODE == 1) {
            const float2 s2 = __ldg((const float2*)(sc0 + cc));
            const float2 h2 = __ldg((const float2*)(sh0 + cc));
            sc0c = s2.x; sc0c1 = s2.y; sh0c = h2.x; sh0c1 = h2.y;
        }
        float s0 = 0.f, s1 = 0.f, q0 = 0.f, q1 = 0.f;
#pragma unroll
        for (int t = 0; t < 2; ++t) {
            const size_t r0 = (size_t)row0 + wr * 32 + t * 16 + (lane >> 2);
            const size_t r1 = r0 + 8;
            const bool ok0 = (MODE != 2) || (r0 < (size_t)N_ATOMS);
            const bool ok1 = (MODE != 2) || (r1 < (size_t)N_ATOMS);
            float v00 = acc[t][j][0] + b2.x;
            float v01 = acc[t][j][1] + b2.y;
            float v10 = acc[t][j][2] + b2.x;
            float v11 = acc[t][j][3] + b2.y;
            if (MODE == 1) {
                const float2 ya = __ldg((const float2*)(y0 + r0 * HIDDEN + cc));
                const float2 yb = __ldg((const float2*)(y0 + r1 * HIDDEN + cc));
                v00 += fmaf(ya.x, sc0c, sh0c);
                v01 += fmaf(ya.y, sc0c1, sh0c1);
                v10 += fmaf(yb.x, sc0c, sh0c);
                v11 += fmaf(yb.y, sc0c1, sh0c1);
            }
            v00 = v00 >= 0.f ? v00 : NEG_SLOPE * v00;
            v01 = v01 >= 0.f ? v01 : NEG_SLOPE * v01;
            v10 = v10 >= 0.f ? v10 : NEG_SLOPE * v10;
            v11 = v11 >= 0.f ? v11 : NEG_SLOPE * v11;
            if (!ok0) { v00 = 0.f; v01 = 0.f; }
            if (!ok1) { v10 = 0.f; v11 = 0.f; }
            if (ok0) *(float2*)(yout + r0 * HIDDEN + cc) = make_float2(v00, v01);
            if (ok1) *(float2*)(yout + r1 * HIDDEN + cc) = make_float2(v10, v11);
            s0 += v00 + v10;
            s1 += v01 + v11;
            q0 += v00 * v00 + v10 * v10;
            q1 += v01 * v01 + v11 * v11;
        }
#pragma unroll
        for (int d = 4; d <= 16; d <<= 1) {
            s0 += __shfl_xor_sync(0xffffffffu, s0, d);
            s1 += __shfl_xor_sync(0xffffffffu, s1, d);
            q0 += __shfl_xor_sync(0xffffffffu, q0, d);
            q1 += __shfl_xor_sync(0xffffffffu, q1, d);
        }
        if ((lane >> 2) == 0) {
            atomicAdd(&s_cs[cc], s0);
            atomicAdd(&s_cs[cc + 1], s1);
            atomicAdd(&s_css[cc], q0);
            atomicAdd(&s_css[cc + 1], q1);
        }
    }
    __syncthreads();
    if (tid < 256) {
        atomicAdd(&g_sum[tid], s_cs[tid]);
        atomicAdd(&g_sumsq[tid], s_css[tid]);
    }
}

// ---------------- BN finalize ------------------------------------------------
__global__ void finalize_kernel(const float* __restrict__ bnw,
                                const float* __restrict__ bnb,
                                float inv_n,
                                float* __restrict__ sc_out,
                                float* __restrict__ sh_out) {
    int o = threadIdx.x;
    float s = g_sum[o], ss = g_sumsq[o];
    float mu = s * inv_n;
    float var = fmaxf(ss * inv_n - mu * mu, 0.f);
    float sc = __ldg(&bnw[o]) * rsqrtf(var + EPS);
    sc_out[o] = sc;
    sh_out[o] = __ldg(&bnb[o]) - mu * sc;
    g_sum[o] = 0.f;
    g_sumsq[o] = 0.f;
}

// ---------------- atom incoming sums (normalized) ----------------------------
__global__ void atom_sum_kernel(const float* __restrict__ y,
                                const int* __restrict__ aibm,
                                const float* __restrict__ sc,
                                const float* __restrict__ sh,
                                float* __restrict__ outp) {
    int gw = (blockIdx.x * blockDim.x + threadIdx.x) >> 5;
    int lane = threadIdx.x & 31;
    if (gw >= N_ATOMS) return;
    float a0 = 0, a1 = 0, a2 = 0, a3 = 0;
    float b0 = 0, b1 = 0, b2 = 0, b3 = 0;
    float cnt = 0.f;
#pragma unroll
    for (int j = 0; j < MAX_DEG; j++) {
        int id = __ldg(&aibm[gw * MAX_DEG + j]);
        if (id > 0) {
            const float4* r = (const float4*)(y + (size_t)(id - 1) * HIDDEN);
            float4 v = __ldg(&r[lane]);
            a0 += v.x; a1 += v.y; a2 += v.z; a3 += v.w;
            float4 w = __ldg(&r[lane + 32]);
            b0 += w.x; b1 += w.y; b2 += w.z; b3 += w.w;
            cnt += 1.f;
        }
    }
    float4 s0 = __ldg((const float4*)sc + lane);
    float4 h0 = __ldg((const float4*)sh + lane);
    float4 s1 = __ldg((const float4*)sc + lane + 32);
    float4 h1 = __ldg((const float4*)sh + lane + 32);
    float4* o = (float4*)(outp + (size_t)gw * HIDDEN);
    o[lane]      = make_float4(fmaf(a0, s0.x, cnt * h0.x), fmaf(a1, s0.y, cnt * h0.y),
                               fmaf(a2, s0.z, cnt * h0.z), fmaf(a3, s0.w, cnt * h0.w));
    o[lane + 32] = make_float4(fmaf(b0, s1.x, cnt * h1.x), fmaf(b1, s1.y, cnt * h1.y),
                               fmaf(b2, s1.z, cnt * h1.z), fmaf(b3, s1.w, cnt * h1.w));
}

// ---------------- output init + pooling --------------------------------------
__global__ void out_init_kernel(const float* __restrict__ molf,
                                float* __restrict__ out) {
    int idx = blockIdx.x * blockDim.x + threadIdx.x;
    if (idx >= N_MOL * OUT_COLS) return;
    int m = idx / OUT_COLS, c = idx % OUT_COLS;
    out[idx] = (c < HIDDEN) ? 0.f : __ldg(&molf[m * MOL_DIM + (c - HIDDEN)]);
}

__global__ void pool_kernel(const float* __restrict__ yv,
                            const int* __restrict__ a2m,
                            const float* __restrict__ sc,
                            const float* __restrict__ sh,
                            float* __restrict__ out) {
    __shared__ int s_mol[32];
    const int c = threadIdx.x;
    const int a0 = blockIdx.x * 32;
    if (c < 32) s_mol[c] = __ldg(&a2m[a0 + c]);
    __syncthreads();
    const float scc = __ldg(&sc[c]);
    const float shc = __ldg(&sh[c]);
    int run = s_mol[0];
    float acc = 0.f;
#pragma unroll 4
    for (int a = 0; a < 32; a++) {
        int m = s_mol[a];
        if (m != run) {
            atomicAdd(&out[(size_t)run * OUT_COLS + c], acc);
            acc = 0.f;
            run = m;
        }
        acc = fmaf(__ldg(&yv[(size_t)(a0 + a) * HIDDEN + c]), scc, acc + shc);
    }
    atomicAdd(&out[(size_t)run * OUT_COLS + c], acc);
}

// ---------------- host launcher ----------------------------------------------
extern "C" void kernel_launch(void* const* d_in, const int* in_sizes, int n_in,
                              void* d_out, int out_size) {
    const float* atomf = (const float*)d_in[0];
    const float* bondf = (const float*)d_in[1];
    const int*   bidx  = (const int*)d_in[2];
    const float* molf  = (const float*)d_in[3];
    const int*   aibm  = (const int*)d_in[4];
    const int*   rev   = (const int*)d_in[5];
    const int*   a2m   = (const int*)d_in[6];
    const float* Wi    = (const float*)d_in[7];
    const float* bi    = (const float*)d_in[8];
    const float* Wm    = (const float*)d_in[9];
    const float* bm    = (const float*)d_in[10];
    const float* Wa    = (const float*)d_in[11];
    const float* ba    = (const float*)d_in[12];
    const float* bnw   = (const float*)d_in[13];
    const float* bnb   = (const float*)d_in[14];
    const int* src = bidx;
    float* out = (float*)d_out;

    float *p_y0, *p_yhA, *p_yhB, *p_asum, *p_yv, *p_sc, *p_sh;
    __nv_bfloat16 *p_WiH, *p_WiL, *p_WmH, *p_WmL, *p_WaH, *p_WaL;
    cudaGetSymbolAddress((void**)&p_y0, g_y0);
    cudaGetSymbolAddress((void**)&p_yhA, g_yhA);
    cudaGetSymbolAddress((void**)&p_yhB, g_yhB);
    cudaGetSymbolAddress((void**)&p_asum, g_asum);
    cudaGetSymbolAddress((void**)&p_yv, g_yv);
    cudaGetSymbolAddress((void**)&p_WiH, g_WiH);
    cudaGetSymbolAddress((void**)&p_WiL, g_WiL);
    cudaGetSymbolAddress((void**)&p_WmH, g_WmH);
    cudaGetSymbolAddress((void**)&p_WmL, g_WmL);
    cudaGetSymbolAddress((void**)&p_WaH, g_WaH);
    cudaGetSymbolAddress((void**)&p_WaL, g_WaL);
    cudaGetSymbolAddress((void**)&p_sc, g_scale);
    cudaGetSymbolAddress((void**)&p_sh, g_shift);
    auto SC = [&](int s) { return p_sc + s * HIDDEN; };
    auto SH = [&](int s) { return p_sh + s * HIDDEN; };

    cudaFuncSetAttribute(gemm_mma<0>, cudaFuncAttributeMaxDynamicSharedMemorySize, SMEM_TOTAL);
    cudaFuncSetAttribute(gemm_mma<1>, cudaFuncAttributeMaxDynamicSharedMemorySize, SMEM_TOTAL);
    cudaFuncSetAttribute(gemm_mma<2>, cudaFuncAttributeMaxDynamicSharedMemorySize, SMEM_TOTAL);

    // split-precision weight prep
    conv_w_kernel<<<(256 * 160 + 255) / 256, 256>>>(Wi, p_WiH, p_WiL, 147, 160);
    conv_w_kernel<<<(256 * 256 + 255) / 256, 256>>>(Wm, p_WmH, p_WmL, 256, 256);
    conv_w_kernel<<<(256 * 416 + 255) / 256, 256>>>(Wa, p_WaH, p_WaL, 389, 416);

    const int GB = N_BONDS / BM;          // 1875
    const int GA = (N_ATOMS + BM - 1) / BM;   // 938 (last block partial)

    // stage 0: h0
    gemm_mma<0><<<GB, THREADS, SMEM_TOTAL>>>(5, bondf, atomf, src, nullptr,
                                             nullptr, nullptr, nullptr, nullptr,
                                             nullptr, nullptr, nullptr,
                                             p_WiH, p_WiL, 160, bi, p_y0);
    finalize_kernel<<<1, 256>>>(bnw, bnb, 1.f / N_BONDS, SC(0), SH(0));

    // depth iterations
    float* ybuf[4] = {p_y0, p_yhA, p_yhB, p_yhA};
    for (int d = 0; d < 3; d++) {
        float* yin = ybuf[d];
        float* yot = ybuf[d + 1];
        atom_sum_kernel<<<N_ATOMS / 8, 256>>>(yin, aibm, SC(d), SH(d), p_asum);
        gemm_mma<1><<<GB, THREADS, SMEM_TOTAL>>>(8, nullptr, nullptr, src, rev,
                                                 p_asum, yin, SC(d), SH(d),
                                                 p_y0, SC(0), SH(0),
                                                 p_WmH, p_WmL, 256, bm, yot);
        finalize_kernel<<<1, 256>>>(bnw, bnb, 1.f / N_BONDS, SC(d + 1), SH(d + 1));
    }

    // final atom readout
    atom_sum_kernel<<<N_ATOMS / 8, 256>>>(ybuf[3], aibm, SC(3), SH(3), p_asum);
    gemm_mma<2><<<GA, THREADS, SMEM_TOTAL>>>(13, nullptr, atomf, nullptr, nullptr,
                                             p_asum, nullptr, nullptr, nullptr,
                                             nullptr, nullptr, nullptr,
                                             p_WaH, p_WaL, 416, ba, p_yv);
    finalize_kernel<<<1, 256>>>(bnw, bnb, 1.f / N_ATOMS, SC(4), SH(4));

    // molecule pooling + feature concat
    out_init_kernel<<<(N_MOL * OUT_COLS + 255) / 256, 256>>>(molf, out);
    pool_kernel<<<N_ATOMS / 32, 256>>>(p_yv, a2m, SC(4), SH(4), out);
}